// round 16
// baseline (speedup 1.0000x reference)
#include <cuda_runtime.h>
#include <cstddef>
#include <cstdint>

// Problem constants
#define BATCH 32
#define NTOK  4900
#define DMODEL 256
#define HEADS 4
#define DH 64
#define WIN 49
#define RATE 5
#define NSEG 20
#define MROWS (BATCH*NTOK)   // 156800
#define GK 256

// Chunked pipeline: 8 chunks x 4 batches
#define NCHUNK 8
#define BATCH_PER_CHUNK 4
#define ROWS_PER_CHUNK (BATCH_PER_CHUNK * NTOK)   // 19600
#define TILES_PER_CHUNK ((ROWS_PER_CHUNK + 127) / 128)  // 154

__device__ float g_q[(size_t)MROWS * DMODEL];
__device__ float g_att[(size_t)MROWS * DMODEL];

__device__ __forceinline__ uint32_t to_tf32(float x) {
    uint32_t y;
    asm("cvt.rna.tf32.f32 %0, %1;" : "=r"(y) : "f"(x));
    return y;
}

__device__ __forceinline__ void mma_tf32_r(float* c,
                                           uint32_t a0, uint32_t a1, uint32_t a2, uint32_t a3,
                                           uint32_t b0, uint32_t b1) {
    asm volatile(
        "mma.sync.aligned.m16n8k8.row.col.f32.tf32.tf32.f32 "
        "{%0,%1,%2,%3}, {%4,%5,%6,%7}, {%8,%9}, {%0,%1,%2,%3};\n"
        : "+f"(c[0]), "+f"(c[1]), "+f"(c[2]), "+f"(c[3])
        : "r"(a0), "r"(a1), "r"(a2), "r"(a3), "r"(b0), "r"(b1));
}

// ---------------------------------------------------------------------------
// TF32 GEMM — R6/R13 mainloop over rows [mStart, mEnd) (unchanged from R15).
// ---------------------------------------------------------------------------
#define ASTR 36
#define TILE_WORDS (128 * ASTR)     // 4608

__global__ __launch_bounds__(256, 2)
void gemm_tf32_kernel(const float* __restrict__ A,
                      const float* __restrict__ Wt,
                      const float* __restrict__ bias,
                      float* __restrict__ C,
                      int mStart, int mEnd) {
    extern __shared__ float smem[];
    float* As0 = smem;
    float* As1 = smem + TILE_WORDS;
    float* Bs0 = smem + 2 * TILE_WORDS;
    float* Bs1 = smem + 3 * TILE_WORDS;

    const int tid  = threadIdx.x;
    const int warp = tid >> 5, lane = tid & 31;
    const int qd = lane >> 2, qq = lane & 3;
    const int wm = warp >> 2;     // 0..1 -> 64 rows
    const int wn = warp & 3;      // 0..3 -> 32 cols
    const int mBase = mStart + blockIdx.y * 128;
    const int nBase = blockIdx.x * 128;

    const float* Wb = Wt + (size_t)nBase * GK;

    float c[4][4][4];
    #pragma unroll
    for (int i = 0; i < 4; i++)
        #pragma unroll
        for (int j = 0; j < 4; j++)
            #pragma unroll
            for (int r = 0; r < 4; r++) c[i][j][r] = 0.f;

    auto issue = [&](float* Ad, float* Bd, int kc) {
        #pragma unroll
        for (int l = 0; l < 4; l++) {
            int idx = l * 256 + tid;
            int m   = idx >> 3;
            int kq  = idx & 7;
            int gm  = mBase + m;
            gm = (gm < mEnd) ? gm : (mEnd - 1);
            uint32_t da = (uint32_t)__cvta_generic_to_shared(&Ad[m * ASTR + kq * 4]);
            const float* sa = A + (size_t)gm * GK + kc * 32 + kq * 4;
            asm volatile("cp.async.cg.shared.global [%0], [%1], 16;\n" :: "r"(da), "l"(sa));
            uint32_t db = (uint32_t)__cvta_generic_to_shared(&Bd[m * ASTR + kq * 4]);
            const float* sb = Wb + (size_t)m * GK + kc * 32 + kq * 4;
            asm volatile("cp.async.cg.shared.global [%0], [%1], 16;\n" :: "r"(db), "l"(sb));
        }
        asm volatile("cp.async.commit_group;\n");
    };

    issue(As0, Bs0, 0);

    const int aRow = wm * 64 + qd;
    const int bRow = wn * 32 + qd;

    #pragma unroll 1
    for (int kc = 0; kc < 8; kc++) {
        const bool even = !(kc & 1);
        const float* Ac = even ? As0 : As1;
        const float* Bc = even ? Bs0 : Bs1;

        if (kc < 7) {
            issue(even ? As1 : As0, even ? Bs1 : Bs0, kc + 1);
            asm volatile("cp.async.wait_group 1;\n");
        } else {
            asm volatile("cp.async.wait_group 0;\n");
        }
        __syncthreads();

        #pragma unroll
        for (int ks = 0; ks < 4; ks++) {
            uint32_t af[4][4];
            #pragma unroll
            for (int i = 0; i < 4; i++) {
                const float* p0 = &Ac[(aRow + i * 16) * ASTR + ks * 8 + qq];
                af[i][0] = to_tf32(p0[0]);
                af[i][2] = to_tf32(p0[4]);
                af[i][1] = to_tf32(p0[8 * ASTR]);
                af[i][3] = to_tf32(p0[8 * ASTR + 4]);
            }
            uint32_t bf[4][2];
            #pragma unroll
            for (int j = 0; j < 4; j++) {
                const float* pb = &Bc[(bRow + j * 8) * ASTR + ks * 8 + qq];
                bf[j][0] = to_tf32(pb[0]);
                bf[j][1] = to_tf32(pb[4]);
            }
            #pragma unroll
            for (int i = 0; i < 4; i++)
                #pragma unroll
                for (int j = 0; j < 4; j++)
                    mma_tf32_r(c[i][j], af[i][0], af[i][1], af[i][2], af[i][3],
                               bf[j][0], bf[j][1]);
        }
        __syncthreads();
    }

    // Epilogue: add bias, write fp32 (guarded to [mStart, mEnd))
    #pragma unroll
    for (int j = 0; j < 4; j++) {
        int col = nBase + wn * 32 + j * 8 + (lane & 3) * 2;
        float b0 = bias[col], b1 = bias[col + 1];
        #pragma unroll
        for (int i = 0; i < 4; i++) {
            int row0 = mBase + wm * 64 + i * 16 + (lane >> 2);
            if (row0 < mEnd) {
                float2 v0 = {c[i][j][0] + b0, c[i][j][1] + b1};
                *reinterpret_cast<float2*>(C + (size_t)row0 * GK + col) = v0;
            }
            if (row0 + 8 < mEnd) {
                float2 v1 = {c[i][j][2] + b0, c[i][j][3] + b1};
                *reinterpret_cast<float2*>(C + (size_t)(row0 + 8) * GK + col) = v1;
            }
        }
    }
}

// ---------------------------------------------------------------------------
// Tensor-core attention (R14, unchanged): one block per (b,g,r,h) in a chunk.
// ---------------------------------------------------------------------------
__global__ __launch_bounds__(128)
void attn_mma_kernel(const float* __restrict__ q, float* __restrict__ out,
                     int bOff) {
    __shared__ uint32_t Xs[64][68];

    int idx = blockIdx.x;
    int h  = idx & 3;
    int r  = (idx >> 2) % RATE;
    int gg = (idx / (RATE * HEADS)) % NSEG;
    int b  = bOff + idx / (RATE * HEADS * NSEG);

    const size_t rowBase = ((size_t)b * NTOK + (size_t)gg * (WIN * RATE) + r);
    const float* base = q + rowBase * DMODEL + h * DH;
    float* obase = out + rowBase * DMODEL + h * DH;

    const int tid  = threadIdx.x;
    const int warp = tid >> 5, lane = tid & 31;
    const int qd = lane >> 2, qq = lane & 3;

    for (int t = tid; t < 7 * 68; t += 128) {
        int rr = t / 68;
        Xs[49 + rr][t - rr * 68] = 0;
    }

    for (int t = tid; t < WIN * 16; t += 128) {
        int row = t >> 4, c4 = t & 15;
        float4 v = *reinterpret_cast<const float4*>(
            base + (size_t)row * (RATE * DMODEL) + c4 * 4);
        *reinterpret_cast<uint4*>(&Xs[row][c4 * 4]) =
            make_uint4(to_tf32(v.x), to_tf32(v.y), to_tf32(v.z), to_tf32(v.w));
    }
    __syncthreads();

    const int mrow = warp * 16;

    float c[7][4];
    #pragma unroll
    for (int nt = 0; nt < 7; nt++)
        #pragma unroll
        for (int k = 0; k < 4; k++) c[nt][k] = 0.f;

    #pragma unroll
    for (int ks = 0; ks < 8; ks++) {
        uint32_t a0 = Xs[mrow + qd][ks * 8 + qq];
        uint32_t a1 = Xs[mrow + qd + 8][ks * 8 + qq];
        uint32_t a2 = Xs[mrow + qd][ks * 8 + qq + 4];
        uint32_t a3 = Xs[mrow + qd + 8][ks * 8 + qq + 4];
        #pragma unroll
        for (int nt = 0; nt < 7; nt++) {
            uint32_t b0 = Xs[nt * 8 + qd][ks * 8 + qq];
            uint32_t b1 = Xs[nt * 8 + qd][ks * 8 + qq + 4];
            mma_tf32_r(c[nt], a0, a1, a2, a3, b0, b1);
        }
    }

    const float scale = 0.125f;
    const float NEG = __int_as_float(0xff800000);
    float m0 = NEG, m1 = NEG;
    #pragma unroll
    for (int nt = 0; nt < 7; nt++)
        #pragma unroll
        for (int par = 0; par < 2; par++) {
            int j = nt * 8 + 2 * qq + par;
            float v0 = (j < WIN) ? c[nt][par] * scale : NEG;
            float v1 = (j < WIN) ? c[nt][par + 2] * scale : NEG;
            c[nt][par] = v0;
            c[nt][par + 2] = v1;
            m0 = fmaxf(m0, v0);
            m1 = fmaxf(m1, v1);
        }
    m0 = fmaxf(m0, __shfl_xor_sync(0xffffffffu, m0, 1));
    m0 = fmaxf(m0, __shfl_xor_sync(0xffffffffu, m0, 2));
    m1 = fmaxf(m1, __shfl_xor_sync(0xffffffffu, m1, 1));
    m1 = fmaxf(m1, __shfl_xor_sync(0xffffffffu, m1, 2));

    float s0 = 0.f, s1 = 0.f;
    #pragma unroll
    for (int nt = 0; nt < 7; nt++)
        #pragma unroll
        for (int par = 0; par < 2; par++) {
            float e0 = __expf(c[nt][par] - m0);
            float e1 = __expf(c[nt][par + 2] - m1);
            c[nt][par] = e0;
            c[nt][par + 2] = e1;
            s0 += e0;
            s1 += e1;
        }
    s0 += __shfl_xor_sync(0xffffffffu, s0, 1);
    s0 += __shfl_xor_sync(0xffffffffu, s0, 2);
    s1 += __shfl_xor_sync(0xffffffffu, s1, 1);
    s1 += __shfl_xor_sync(0xffffffffu, s1, 2);
    float inv0 = 1.f / s0, inv1 = 1.f / s1;

    float o[8][4];
    #pragma unroll
    for (int nt = 0; nt < 8; nt++)
        #pragma unroll
        for (int k = 0; k < 4; k++) o[nt][k] = 0.f;

    const int srcA = (lane & ~3) + (qq >> 1);
    const bool odd = (qq & 1);

    #pragma unroll
    for (int ks = 0; ks < 7; ks++) {
        float v0 = __shfl_sync(0xffffffffu, c[ks][0], srcA);
        float v1 = __shfl_sync(0xffffffffu, c[ks][1], srcA);
        float v2 = __shfl_sync(0xffffffffu, c[ks][2], srcA);
        float v3 = __shfl_sync(0xffffffffu, c[ks][3], srcA);
        float w0 = __shfl_sync(0xffffffffu, c[ks][0], srcA + 2);
        float w1 = __shfl_sync(0xffffffffu, c[ks][1], srcA + 2);
        float w2 = __shfl_sync(0xffffffffu, c[ks][2], srcA + 2);
        float w3 = __shfl_sync(0xffffffffu, c[ks][3], srcA + 2);
        uint32_t a0 = to_tf32(odd ? v1 : v0);
        uint32_t a1 = to_tf32(odd ? v3 : v2);
        uint32_t a2 = to_tf32(odd ? w1 : w0);
        uint32_t a3 = to_tf32(odd ? w3 : w2);
        #pragma unroll
        for (int nt = 0; nt < 8; nt++) {
            uint32_t b0 = Xs[ks * 8 + qq][nt * 8 + qd];
            uint32_t b1 = Xs[ks * 8 + qq + 4][nt * 8 + qd];
            mma_tf32_r(o[nt], a0, a1, a2, a3, b0, b1);
        }
    }

    const int r0 = mrow + qd, r1 = r0 + 8;
    #pragma unroll
    for (int nt = 0; nt < 8; nt++) {
        int col = nt * 8 + 2 * qq;
        if (r0 < WIN) {
            float2 v = {o[nt][0] * inv0, o[nt][1] * inv0};
            *reinterpret_cast<float2*>(obase + (size_t)r0 * (RATE * DMODEL) + col) = v;
        }
        if (r1 < WIN) {
            float2 v = {o[nt][2] * inv1, o[nt][3] * inv1};
            *reinterpret_cast<float2*>(obase + (size_t)r1 * (RATE * DMODEL) + col) = v;
        }
    }
}

// ---------------------------------------------------------------------------
// Launch: asymmetric pipeline — sG runs ALL GEMMs back-to-back (software-
// pipelined one chunk ahead), sA runs ALL attentions; per-chunk deps via
// events (proj1_i -> attn_i -> proj2_i). Attention hides under the next
// chunk's proj1 instead of contending GEMM-vs-GEMM.
// ---------------------------------------------------------------------------
extern "C" void kernel_launch(void* const* d_in, const int* in_sizes, int n_in,
                              void* d_out, int out_size) {
    const float* emb = (const float*)d_in[0];
    const float* Wq  = (const float*)d_in[1];
    const float* bq  = (const float*)d_in[2];
    const float* Wo  = (const float*)d_in[3];
    const float* bo  = (const float*)d_in[4];
    float* outp = (float*)d_out;

    float *qbuf = nullptr, *abuf = nullptr;
    cudaGetSymbolAddress((void**)&qbuf, g_q);
    cudaGetSymbolAddress((void**)&abuf, g_att);

    const int smemBytes = 4 * TILE_WORDS * 4;   // 73728
    static cudaStream_t sG, sA;
    static cudaEvent_t eFork, eJoinG, eJoinA;
    static cudaEvent_t g1[NCHUNK], a[NCHUNK];
    static bool inited = false;
    if (!inited) {
        cudaFuncSetAttribute(gemm_tf32_kernel,
                             cudaFuncAttributeMaxDynamicSharedMemorySize, smemBytes);
        cudaStreamCreateWithFlags(&sG, cudaStreamNonBlocking);
        cudaStreamCreateWithFlags(&sA, cudaStreamNonBlocking);
        cudaEventCreateWithFlags(&eFork,  cudaEventDisableTiming);
        cudaEventCreateWithFlags(&eJoinG, cudaEventDisableTiming);
        cudaEventCreateWithFlags(&eJoinA, cudaEventDisableTiming);
        for (int i = 0; i < NCHUNK; i++) {
            cudaEventCreateWithFlags(&g1[i], cudaEventDisableTiming);
            cudaEventCreateWithFlags(&a[i],  cudaEventDisableTiming);
        }
        inited = true;
    }

    // Fork from the (captured) default stream
    cudaEventRecord(eFork, 0);
    cudaStreamWaitEvent(sG, eFork, 0);
    cudaStreamWaitEvent(sA, eFork, 0);

    dim3 ggrid(DMODEL / 128, TILES_PER_CHUNK);   // (2, 154)

    // Prologue: proj1_0
    {
        int mS = 0, mE = ROWS_PER_CHUNK;
        gemm_tf32_kernel<<<ggrid, 256, smemBytes, sG>>>(emb, Wq, bq, qbuf, mS, mE);
        cudaEventRecord(g1[0], sG);
    }

    for (int i = 0; i < NCHUNK; i++) {
        // Issue next chunk's proj1 on sG ahead of this chunk's proj2
        if (i + 1 < NCHUNK) {
            int mS = (i + 1) * ROWS_PER_CHUNK, mE = mS + ROWS_PER_CHUNK;
            gemm_tf32_kernel<<<ggrid, 256, smemBytes, sG>>>(emb, Wq, bq, qbuf, mS, mE);
            cudaEventRecord(g1[i + 1], sG);
        }
        // attn_i on sA (waits proj1_i)
        cudaStreamWaitEvent(sA, g1[i], 0);
        attn_mma_kernel<<<BATCH_PER_CHUNK * NSEG * RATE * HEADS, 128, 0, sA>>>(
            qbuf, abuf, i * BATCH_PER_CHUNK);
        cudaEventRecord(a[i], sA);
        // proj2_i on sG (waits attn_i)
        cudaStreamWaitEvent(sG, a[i], 0);
        {
            int mS = i * ROWS_PER_CHUNK, mE = mS + ROWS_PER_CHUNK;
            gemm_tf32_kernel<<<ggrid, 256, smemBytes, sG>>>(abuf, Wo, bo, outp, mS, mE);
        }
    }

    // Join back to the default stream
    cudaEventRecord(eJoinG, sG);
    cudaEventRecord(eJoinA, sA);
    cudaStreamWaitEvent(0, eJoinG, 0);
    cudaStreamWaitEvent(0, eJoinA, 0);
}

// round 17
// speedup vs baseline: 1.1568x; 1.1568x over previous
#include <cuda_runtime.h>
#include <cstddef>
#include <cstdint>

// Problem constants
#define BATCH 32
#define NTOK  4900
#define DMODEL 256
#define HEADS 4
#define DH 64
#define WIN 49
#define RATE 5
#define NSEG 20
#define MROWS (BATCH*NTOK)   // 156800
#define GK 256

// 2-chunk wave-aligned pipeline (148 SMs x 2 CTAs = 296 resident blocks):
//   proj1 chunk0: rows [0, 75776)        -> y=592 -> 1184 blocks = 4.00 waves
//   proj1 chunk1: rows [75776, 156800)   -> y=633
//   attn  chunk0: batches 0..14 ; chunk1: batches 15..31
//   proj2 chunk0: rows [0, 73500) ; chunk1: rows [73500, 156800)
#define P1_SPLIT 75776
#define AT_SPLIT_B 15
#define P2_SPLIT (AT_SPLIT_B * NTOK)   // 73500

__device__ float g_q[(size_t)MROWS * DMODEL];
__device__ float g_att[(size_t)MROWS * DMODEL];

__device__ __forceinline__ uint32_t to_tf32(float x) {
    uint32_t y;
    asm("cvt.rna.tf32.f32 %0, %1;" : "=r"(y) : "f"(x));
    return y;
}

__device__ __forceinline__ void mma_tf32_r(float* c,
                                           uint32_t a0, uint32_t a1, uint32_t a2, uint32_t a3,
                                           uint32_t b0, uint32_t b1) {
    asm volatile(
        "mma.sync.aligned.m16n8k8.row.col.f32.tf32.tf32.f32 "
        "{%0,%1,%2,%3}, {%4,%5,%6,%7}, {%8,%9}, {%0,%1,%2,%3};\n"
        : "+f"(c[0]), "+f"(c[1]), "+f"(c[2]), "+f"(c[3])
        : "r"(a0), "r"(a1), "r"(a2), "r"(a3), "r"(b0), "r"(b1));
}

// ---------------------------------------------------------------------------
// TF32 GEMM — R6/R13 mainloop over rows [mStart, mEnd) (unchanged).
// ---------------------------------------------------------------------------
#define ASTR 36
#define TILE_WORDS (128 * ASTR)     // 4608

__global__ __launch_bounds__(256, 2)
void gemm_tf32_kernel(const float* __restrict__ A,
                      const float* __restrict__ Wt,
                      const float* __restrict__ bias,
                      float* __restrict__ C,
                      int mStart, int mEnd) {
    extern __shared__ float smem[];
    float* As0 = smem;
    float* As1 = smem + TILE_WORDS;
    float* Bs0 = smem + 2 * TILE_WORDS;
    float* Bs1 = smem + 3 * TILE_WORDS;

    const int tid  = threadIdx.x;
    const int warp = tid >> 5, lane = tid & 31;
    const int qd = lane >> 2, qq = lane & 3;
    const int wm = warp >> 2;     // 0..1 -> 64 rows
    const int wn = warp & 3;      // 0..3 -> 32 cols
    const int mBase = mStart + blockIdx.y * 128;
    const int nBase = blockIdx.x * 128;

    const float* Wb = Wt + (size_t)nBase * GK;

    float c[4][4][4];
    #pragma unroll
    for (int i = 0; i < 4; i++)
        #pragma unroll
        for (int j = 0; j < 4; j++)
            #pragma unroll
            for (int r = 0; r < 4; r++) c[i][j][r] = 0.f;

    auto issue = [&](float* Ad, float* Bd, int kc) {
        #pragma unroll
        for (int l = 0; l < 4; l++) {
            int idx = l * 256 + tid;
            int m   = idx >> 3;
            int kq  = idx & 7;
            int gm  = mBase + m;
            gm = (gm < mEnd) ? gm : (mEnd - 1);
            uint32_t da = (uint32_t)__cvta_generic_to_shared(&Ad[m * ASTR + kq * 4]);
            const float* sa = A + (size_t)gm * GK + kc * 32 + kq * 4;
            asm volatile("cp.async.cg.shared.global [%0], [%1], 16;\n" :: "r"(da), "l"(sa));
            uint32_t db = (uint32_t)__cvta_generic_to_shared(&Bd[m * ASTR + kq * 4]);
            const float* sb = Wb + (size_t)m * GK + kc * 32 + kq * 4;
            asm volatile("cp.async.cg.shared.global [%0], [%1], 16;\n" :: "r"(db), "l"(sb));
        }
        asm volatile("cp.async.commit_group;\n");
    };

    issue(As0, Bs0, 0);

    const int aRow = wm * 64 + qd;
    const int bRow = wn * 32 + qd;

    #pragma unroll 1
    for (int kc = 0; kc < 8; kc++) {
        const bool even = !(kc & 1);
        const float* Ac = even ? As0 : As1;
        const float* Bc = even ? Bs0 : Bs1;

        if (kc < 7) {
            issue(even ? As1 : As0, even ? Bs1 : Bs0, kc + 1);
            asm volatile("cp.async.wait_group 1;\n");
        } else {
            asm volatile("cp.async.wait_group 0;\n");
        }
        __syncthreads();

        #pragma unroll
        for (int ks = 0; ks < 4; ks++) {
            uint32_t af[4][4];
            #pragma unroll
            for (int i = 0; i < 4; i++) {
                const float* p0 = &Ac[(aRow + i * 16) * ASTR + ks * 8 + qq];
                af[i][0] = to_tf32(p0[0]);
                af[i][2] = to_tf32(p0[4]);
                af[i][1] = to_tf32(p0[8 * ASTR]);
                af[i][3] = to_tf32(p0[8 * ASTR + 4]);
            }
            uint32_t bf[4][2];
            #pragma unroll
            for (int j = 0; j < 4; j++) {
                const float* pb = &Bc[(bRow + j * 8) * ASTR + ks * 8 + qq];
                bf[j][0] = to_tf32(pb[0]);
                bf[j][1] = to_tf32(pb[4]);
            }
            #pragma unroll
            for (int i = 0; i < 4; i++)
                #pragma unroll
                for (int j = 0; j < 4; j++)
                    mma_tf32_r(c[i][j], af[i][0], af[i][1], af[i][2], af[i][3],
                               bf[j][0], bf[j][1]);
        }
        __syncthreads();
    }

    // Epilogue: add bias, write fp32 (guarded to [mStart, mEnd))
    #pragma unroll
    for (int j = 0; j < 4; j++) {
        int col = nBase + wn * 32 + j * 8 + (lane & 3) * 2;
        float b0 = bias[col], b1 = bias[col + 1];
        #pragma unroll
        for (int i = 0; i < 4; i++) {
            int row0 = mBase + wm * 64 + i * 16 + (lane >> 2);
            if (row0 < mEnd) {
                float2 v0 = {c[i][j][0] + b0, c[i][j][1] + b1};
                *reinterpret_cast<float2*>(C + (size_t)row0 * GK + col) = v0;
            }
            if (row0 + 8 < mEnd) {
                float2 v1 = {c[i][j][2] + b0, c[i][j][3] + b1};
                *reinterpret_cast<float2*>(C + (size_t)(row0 + 8) * GK + col) = v1;
            }
        }
    }
}

// ---------------------------------------------------------------------------
// Tensor-core attention (R14, unchanged): one block per (b,g,r,h) in a chunk.
// ---------------------------------------------------------------------------
__global__ __launch_bounds__(128)
void attn_mma_kernel(const float* __restrict__ q, float* __restrict__ out,
                     int bOff) {
    __shared__ uint32_t Xs[64][68];

    int idx = blockIdx.x;
    int h  = idx & 3;
    int r  = (idx >> 2) % RATE;
    int gg = (idx / (RATE * HEADS)) % NSEG;
    int b  = bOff + idx / (RATE * HEADS * NSEG);

    const size_t rowBase = ((size_t)b * NTOK + (size_t)gg * (WIN * RATE) + r);
    const float* base = q + rowBase * DMODEL + h * DH;
    float* obase = out + rowBase * DMODEL + h * DH;

    const int tid  = threadIdx.x;
    const int warp = tid >> 5, lane = tid & 31;
    const int qd = lane >> 2, qq = lane & 3;

    for (int t = tid; t < 7 * 68; t += 128) {
        int rr = t / 68;
        Xs[49 + rr][t - rr * 68] = 0;
    }

    for (int t = tid; t < WIN * 16; t += 128) {
        int row = t >> 4, c4 = t & 15;
        float4 v = *reinterpret_cast<const float4*>(
            base + (size_t)row * (RATE * DMODEL) + c4 * 4);
        *reinterpret_cast<uint4*>(&Xs[row][c4 * 4]) =
            make_uint4(to_tf32(v.x), to_tf32(v.y), to_tf32(v.z), to_tf32(v.w));
    }
    __syncthreads();

    const int mrow = warp * 16;

    float c[7][4];
    #pragma unroll
    for (int nt = 0; nt < 7; nt++)
        #pragma unroll
        for (int k = 0; k < 4; k++) c[nt][k] = 0.f;

    #pragma unroll
    for (int ks = 0; ks < 8; ks++) {
        uint32_t a0 = Xs[mrow + qd][ks * 8 + qq];
        uint32_t a1 = Xs[mrow + qd + 8][ks * 8 + qq];
        uint32_t a2 = Xs[mrow + qd][ks * 8 + qq + 4];
        uint32_t a3 = Xs[mrow + qd + 8][ks * 8 + qq + 4];
        #pragma unroll
        for (int nt = 0; nt < 7; nt++) {
            uint32_t b0 = Xs[nt * 8 + qd][ks * 8 + qq];
            uint32_t b1 = Xs[nt * 8 + qd][ks * 8 + qq + 4];
            mma_tf32_r(c[nt], a0, a1, a2, a3, b0, b1);
        }
    }

    const float scale = 0.125f;
    const float NEG = __int_as_float(0xff800000);
    float m0 = NEG, m1 = NEG;
    #pragma unroll
    for (int nt = 0; nt < 7; nt++)
        #pragma unroll
        for (int par = 0; par < 2; par++) {
            int j = nt * 8 + 2 * qq + par;
            float v0 = (j < WIN) ? c[nt][par] * scale : NEG;
            float v1 = (j < WIN) ? c[nt][par + 2] * scale : NEG;
            c[nt][par] = v0;
            c[nt][par + 2] = v1;
            m0 = fmaxf(m0, v0);
            m1 = fmaxf(m1, v1);
        }
    m0 = fmaxf(m0, __shfl_xor_sync(0xffffffffu, m0, 1));
    m0 = fmaxf(m0, __shfl_xor_sync(0xffffffffu, m0, 2));
    m1 = fmaxf(m1, __shfl_xor_sync(0xffffffffu, m1, 1));
    m1 = fmaxf(m1, __shfl_xor_sync(0xffffffffu, m1, 2));

    float s0 = 0.f, s1 = 0.f;
    #pragma unroll
    for (int nt = 0; nt < 7; nt++)
        #pragma unroll
        for (int par = 0; par < 2; par++) {
            float e0 = __expf(c[nt][par] - m0);
            float e1 = __expf(c[nt][par + 2] - m1);
            c[nt][par] = e0;
            c[nt][par + 2] = e1;
            s0 += e0;
            s1 += e1;
        }
    s0 += __shfl_xor_sync(0xffffffffu, s0, 1);
    s0 += __shfl_xor_sync(0xffffffffu, s0, 2);
    s1 += __shfl_xor_sync(0xffffffffu, s1, 1);
    s1 += __shfl_xor_sync(0xffffffffu, s1, 2);
    float inv0 = 1.f / s0, inv1 = 1.f / s1;

    float o[8][4];
    #pragma unroll
    for (int nt = 0; nt < 8; nt++)
        #pragma unroll
        for (int k = 0; k < 4; k++) o[nt][k] = 0.f;

    const int srcA = (lane & ~3) + (qq >> 1);
    const bool odd = (qq & 1);

    #pragma unroll
    for (int ks = 0; ks < 7; ks++) {
        float v0 = __shfl_sync(0xffffffffu, c[ks][0], srcA);
        float v1 = __shfl_sync(0xffffffffu, c[ks][1], srcA);
        float v2 = __shfl_sync(0xffffffffu, c[ks][2], srcA);
        float v3 = __shfl_sync(0xffffffffu, c[ks][3], srcA);
        float w0 = __shfl_sync(0xffffffffu, c[ks][0], srcA + 2);
        float w1 = __shfl_sync(0xffffffffu, c[ks][1], srcA + 2);
        float w2 = __shfl_sync(0xffffffffu, c[ks][2], srcA + 2);
        float w3 = __shfl_sync(0xffffffffu, c[ks][3], srcA + 2);
        uint32_t a0 = to_tf32(odd ? v1 : v0);
        uint32_t a1 = to_tf32(odd ? v3 : v2);
        uint32_t a2 = to_tf32(odd ? w1 : w0);
        uint32_t a3 = to_tf32(odd ? w3 : w2);
        #pragma unroll
        for (int nt = 0; nt < 8; nt++) {
            uint32_t b0 = Xs[ks * 8 + qq][nt * 8 + qd];
            uint32_t b1 = Xs[ks * 8 + qq + 4][nt * 8 + qd];
            mma_tf32_r(o[nt], a0, a1, a2, a3, b0, b1);
        }
    }

    const int r0 = mrow + qd, r1 = r0 + 8;
    #pragma unroll
    for (int nt = 0; nt < 8; nt++) {
        int col = nt * 8 + 2 * qq;
        if (r0 < WIN) {
            float2 v = {o[nt][0] * inv0, o[nt][1] * inv0};
            *reinterpret_cast<float2*>(obase + (size_t)r0 * (RATE * DMODEL) + col) = v;
        }
        if (r1 < WIN) {
            float2 v = {o[nt][2] * inv1, o[nt][3] * inv1};
            *reinterpret_cast<float2*>(obase + (size_t)r1 * (RATE * DMODEL) + col) = v;
        }
    }
}

// ---------------------------------------------------------------------------
// Launch: 2-chunk asymmetric pipeline, wave-aligned GEMM chunks.
//   sG: proj1_0 | proj1_1 | [a0] proj2_0 | [a1] proj2_1
//   sA:          [g1_0] attn_0 | [g1_1] attn_1
// ---------------------------------------------------------------------------
extern "C" void kernel_launch(void* const* d_in, const int* in_sizes, int n_in,
                              void* d_out, int out_size) {
    const float* emb = (const float*)d_in[0];
    const float* Wq  = (const float*)d_in[1];
    const float* bq  = (const float*)d_in[2];
    const float* Wo  = (const float*)d_in[3];
    const float* bo  = (const float*)d_in[4];
    float* outp = (float*)d_out;

    float *qbuf = nullptr, *abuf = nullptr;
    cudaGetSymbolAddress((void**)&qbuf, g_q);
    cudaGetSymbolAddress((void**)&abuf, g_att);

    const int smemBytes = 4 * TILE_WORDS * 4;   // 73728
    static cudaStream_t sG, sA;
    static cudaEvent_t eFork, eJoinG, eJoinA;
    static cudaEvent_t g1[2], a[2];
    static bool inited = false;
    if (!inited) {
        cudaFuncSetAttribute(gemm_tf32_kernel,
                             cudaFuncAttributeMaxDynamicSharedMemorySize, smemBytes);
        cudaStreamCreateWithFlags(&sG, cudaStreamNonBlocking);
        cudaStreamCreateWithFlags(&sA, cudaStreamNonBlocking);
        cudaEventCreateWithFlags(&eFork,  cudaEventDisableTiming);
        cudaEventCreateWithFlags(&eJoinG, cudaEventDisableTiming);
        cudaEventCreateWithFlags(&eJoinA, cudaEventDisableTiming);
        for (int i = 0; i < 2; i++) {
            cudaEventCreateWithFlags(&g1[i], cudaEventDisableTiming);
            cudaEventCreateWithFlags(&a[i],  cudaEventDisableTiming);
        }
        inited = true;
    }

    // Fork from the (captured) default stream
    cudaEventRecord(eFork, 0);
    cudaStreamWaitEvent(sG, eFork, 0);
    cudaStreamWaitEvent(sA, eFork, 0);

    // proj1 chunks (wave-aligned: 592 y-tiles = 1184 blocks = 4.00 waves)
    {
        dim3 g0(DMODEL / 128, P1_SPLIT / 128);               // (2, 592)
        gemm_tf32_kernel<<<g0, 256, smemBytes, sG>>>(emb, Wq, bq, qbuf, 0, P1_SPLIT);
        cudaEventRecord(g1[0], sG);
        dim3 g1g(DMODEL / 128, (MROWS - P1_SPLIT) / 128);    // (2, 633)
        gemm_tf32_kernel<<<g1g, 256, smemBytes, sG>>>(emb, Wq, bq, qbuf, P1_SPLIT, MROWS);
        cudaEventRecord(g1[1], sG);
    }

    // attention chunks on sA
    cudaStreamWaitEvent(sA, g1[0], 0);
    attn_mma_kernel<<<AT_SPLIT_B * NSEG * RATE * HEADS, 128, 0, sA>>>(qbuf, abuf, 0);
    cudaEventRecord(a[0], sA);
    cudaStreamWaitEvent(sA, g1[1], 0);
    attn_mma_kernel<<<(BATCH - AT_SPLIT_B) * NSEG * RATE * HEADS, 128, 0, sA>>>(
        qbuf, abuf, AT_SPLIT_B);
    cudaEventRecord(a[1], sA);

    // proj2 chunks on sG
    cudaStreamWaitEvent(sG, a[0], 0);
    {
        dim3 g2(DMODEL / 128, (P2_SPLIT + 127) / 128);       // (2, 575)
        gemm_tf32_kernel<<<g2, 256, smemBytes, sG>>>(abuf, Wo, bo, outp, 0, P2_SPLIT);
    }
    cudaStreamWaitEvent(sG, a[1], 0);
    {
        dim3 g3(DMODEL / 128, (MROWS - P2_SPLIT + 127) / 128);  // (2, 651)
        gemm_tf32_kernel<<<g3, 256, smemBytes, sG>>>(abuf, Wo, bo, outp, P2_SPLIT, MROWS);
    }

    // Join back to the default stream
    cudaEventRecord(eJoinG, sG);
    cudaEventRecord(eJoinA, sA);
    cudaStreamWaitEvent(0, eJoinG, 0);
    cudaStreamWaitEvent(0, eJoinA, 0);
}